// round 6
// baseline (speedup 1.0000x reference)
#include <cuda_runtime.h>
#include <cstdint>

typedef long long ll;

#define BATCH 8192
#define INS   1024
#define GG    1024
#define HS    2048
#define KTOT  2048

#define BM 128
#define BN 256
#define BK 32
#define NKI (KTOT/BK)     // 64 K-stages
#define STAGES 4

#define A_BYTES (BM*BK*4)     // 16384
#define B_BYTES (BN*BK*4)     // 32768
#define A_OFF  0
#define B_OFF  (A_OFF + STAGES*A_BYTES)
#define SMEM_TOTAL (B_OFF + STAGES*B_BYTES)   // 196608

// ---------------- scratch ----------------
__device__ float g_HA[(size_t)BATCH * GG];   // h2_fl, later h1_fl
__device__ float g_HB[(size_t)BATCH * GG];   // r * h_fl
__device__ float g_Z [(size_t)BATCH * GG];   // z1, later z2
__device__ double g_bp1[512];
__device__ double g_bp2[512];

// ---------------- helpers ----------------
__device__ __forceinline__ uint32_t smaddr(const void* p) {
    return (uint32_t)__cvta_generic_to_shared(p);
}
__device__ __forceinline__ void cp16(uint32_t d, const void* s) {
    asm volatile("cp.async.cg.shared.global [%0], [%1], 16;\n" :: "r"(d), "l"(s));
}
__device__ __forceinline__ void cpcommit() { asm volatile("cp.async.commit_group;\n" ::); }
template<int N> __device__ __forceinline__ void cpwait() {
    asm volatile("cp.async.wait_group %0;\n" :: "n"(N));
}

// legacy m16n8k8 tf32 mma (valid on base sm_103 target)
__device__ __forceinline__ void mma_tf32(float* d, const uint32_t* a, const uint32_t* b) {
    asm volatile(
        "mma.sync.aligned.m16n8k8.row.col.f32.tf32.tf32.f32 "
        "{%0,%1,%2,%3}, {%4,%5,%6,%7}, {%8,%9}, {%0,%1,%2,%3};\n"
        : "+f"(d[0]), "+f"(d[1]), "+f"(d[2]), "+f"(d[3])
        : "r"(a[0]), "r"(a[1]), "r"(a[2]), "r"(a[3]), "r"(b[0]), "r"(b[1]));
}

__device__ __forceinline__ float sigf(float v) { return 1.0f / (1.0f + expf(-v)); }
__device__ __forceinline__ void hupd(float pre, float z, int h, float* rec, float* oh) {
    float gv = tanhf(pre);
    ll zf = (ll)(z * 1024.0f); if (zf < 1) zf = 1;
    int hi = (int)((((ll)h * zf) >> 10) + (ll)((1.0f - z) * gv * 8388608.0f));
    *rec = (float)hi; *oh = (float)hi * (1.0f / 8388608.0f);
}

// ---------------- GEMM with fused epilogue ----------------
// EPI 0: zr GEMM (N grid = 2048). cols<1024: z=0.875*sig+0.125 -> g_Z, plus
//        fused bits partial (-log2 z over cols >= slice) -> g_bp{1,2}[cta]
//        (selected by `which` INSIDE device code — __device__ symbols are
//        not valid as host-passed pointers).
//        cols>=1024: g_HB = sig * g_HA.
// EPI 1: g GEMM (N grid = 1024). tanh + fixed-point hidden update; writes
//        recurrent + output_hidden (+ g_HA = h1_fl when writeHA).
template<int EPI>
__global__ void __launch_bounds__(256, 1) gemm_k(
    const float* __restrict__ x,
    const float* __restrict__ W,     // [KTOT][Ncols] row-major, read directly
    const float* __restrict__ bias,
    int Ncols,
    int hinSel,
    const int* __restrict__ hidden,
    int hoff,
    float* __restrict__ out,
    int writeHA,
    const int* __restrict__ slice_ptr,
    int which)
{
    extern __shared__ char smem[];
    const uint32_t sbase = smaddr(smem);
    const int tid  = threadIdx.x;
    const int wid  = tid >> 5, lane = tid & 31;
    const int bm0  = blockIdx.y * BM;
    const int bn0  = blockIdx.x * BN;
    const float* Hin = hinSel ? g_HB : g_HA;

    // A smem: [m][k] 128B rows, chunk XOR (m&7)<<4
    // B smem: [k][n] 1024B rows, chunk XOR (k&3)<<5
    auto load_stage = [&](int kt, int buf) {
        const int kbase = kt * BK;
        const float* asrc = (kbase < INS) ? (x + kbase) : (Hin + (kbase - INS));
        const uint32_t abase = sbase + A_OFF + buf * A_BYTES;
        #pragma unroll
        for (int i = 0; i < 4; ++i) {
            int q = tid + i * 256;
            int row = q >> 3, kc = q & 7;                       // kc: 16B chunk in row
            uint32_t off = row * 128 + ((kc * 16) ^ ((row & 7) << 4));
            cp16(abase + off, asrc + (size_t)(bm0 + row) * INS + kc * 4);
        }
        const uint32_t bbase = sbase + B_OFF + buf * B_BYTES;
        #pragma unroll
        for (int i = 0; i < 8; ++i) {
            int q = tid + i * 256;
            int kr = q >> 6, c = q & 63;                        // c: 16B chunk in row
            uint32_t off = kr * 1024 + ((c * 16) ^ ((kr & 3) << 5));
            cp16(bbase + off, W + (size_t)(kbase + kr) * Ncols + bn0 + c * 4);
        }
    };

    #pragma unroll
    for (int s = 0; s < STAGES - 1; ++s) { load_stage(s, s); cpcommit(); }

    // 8 warps: 2(M) x 4(N); warp tile 64x64
    const int wm0 = (wid >> 2) * 64;
    const int wn0 = (wid & 3) * 64;
    const int rm = lane >> 2, ck = lane & 3;
    float acc[4][8][4];
    #pragma unroll
    for (int i = 0; i < 4; ++i)
        #pragma unroll
        for (int j = 0; j < 8; ++j)
            #pragma unroll
            for (int e = 0; e < 4; ++e) acc[i][j][e] = 0.0f;

    for (int kt = 0; kt < NKI; ++kt) {
        const int buf = kt & (STAGES - 1);
        const int lt = kt + STAGES - 1;
        if (lt < NKI) load_stage(lt, lt & (STAGES - 1));
        cpcommit();
        cpwait<STAGES - 1>();
        __syncthreads();

        const char* At = smem + A_OFF + buf * A_BYTES;
        const char* Bt = smem + B_OFF + buf * B_BYTES;
        #pragma unroll
        for (int ks = 0; ks < 4; ++ks) {
            const int k0 = ks * 8;
            uint32_t af[4][4];
            #pragma unroll
            for (int mi = 0; mi < 4; ++mi) {
                int m1 = wm0 + mi * 16 + rm;
                int m2 = m1 + 8;
                uint32_t o;
                o = m1 * 128 + (((k0 + ck) * 4)     ^ ((m1 & 7) << 4));
                af[mi][0] = *(const uint32_t*)(At + o);
                o = m2 * 128 + (((k0 + ck) * 4)     ^ ((m2 & 7) << 4));
                af[mi][1] = *(const uint32_t*)(At + o);
                o = m1 * 128 + (((k0 + ck + 4) * 4) ^ ((m1 & 7) << 4));
                af[mi][2] = *(const uint32_t*)(At + o);
                o = m2 * 128 + (((k0 + ck + 4) * 4) ^ ((m2 & 7) << 4));
                af[mi][3] = *(const uint32_t*)(At + o);
            }
            #pragma unroll
            for (int ni = 0; ni < 8; ++ni) {
                int n = wn0 + ni * 8 + rm;
                int ka = k0 + ck, kb = k0 + ck + 4;
                uint32_t bf[2];
                bf[0] = *(const uint32_t*)(Bt + ka * 1024 + ((n * 4) ^ ((ka & 3) << 5)));
                bf[1] = *(const uint32_t*)(Bt + kb * 1024 + ((n * 4) ^ ((kb & 3) << 5)));
                #pragma unroll
                for (int mi = 0; mi < 4; ++mi)
                    mma_tf32(acc[mi][ni], af[mi], bf);
            }
        }
        __syncthreads();
    }

    // ---------------- epilogue ----------------
    const int c2 = (lane & 3) * 2;
    float bl = 0.0f;                               // fused bits partial (EPI0, z side)
    const int slice = (EPI == 0 && slice_ptr) ? __ldg(slice_ptr) : 0;

    #pragma unroll
    for (int mi = 0; mi < 4; ++mi) {
        #pragma unroll
        for (int rr = 0; rr < 2; ++rr) {
            int m = bm0 + wm0 + mi * 16 + rm + rr * 8;
            #pragma unroll
            for (int ni = 0; ni < 8; ++ni) {
                int n = bn0 + wn0 + ni * 8 + c2;
                float p0 = acc[mi][ni][rr * 2 + 0] + bias[n];
                float p1 = acc[mi][ni][rr * 2 + 1] + bias[n + 1];
                if (EPI == 0) {
                    float s0 = sigf(p0), s1 = sigf(p1);
                    if (n < GG) {
                        float2 z; z.x = 0.875f * s0 + 0.125f; z.y = 0.875f * s1 + 0.125f;
                        *(float2*)&g_Z[(size_t)m * GG + n] = z;
                        if (n     >= slice) bl -= log2f(z.x);
                        if (n + 1 >= slice) bl -= log2f(z.y);
                    } else {
                        size_t j = (size_t)m * GG + (n - GG);
                        float2 ha = *(const float2*)&g_HA[j];
                        float2 hb; hb.x = s0 * ha.x; hb.y = s1 * ha.y;
                        *(float2*)&g_HB[j] = hb;
                    }
                } else {
                    size_t zj = (size_t)m * GG + n;
                    float2 zv = *(const float2*)&g_Z[zj];
                    int2 hv = *(const int2*)&hidden[(size_t)m * HS + hoff + n];
                    float2 recf, ohf;
                    hupd(p0, zv.x, hv.x, &recf.x, &ohf.x);
                    hupd(p1, zv.y, hv.y, &recf.y, &ohf.y);
                    *(float2*)&out[(size_t)m * HS + hoff + n] = recf;
                    *(float2*)&out[(size_t)BATCH * HS + (size_t)m * HS + hoff + n] = ohf;
                    if (writeHA) *(float2*)&g_HA[zj] = ohf;
                }
            }
        }
    }

    if (EPI == 0) {
        // deterministic per-CTA reduction of bits partial
        #pragma unroll
        for (int o = 16; o > 0; o >>= 1)
            bl += __shfl_down_sync(0xFFFFFFFFu, bl, o);
        __shared__ double wsum[8];
        if (lane == 0) wsum[wid] = (double)bl;
        __syncthreads();
        if (tid == 0) {
            double s = 0.0;
            #pragma unroll
            for (int i = 0; i < 8; ++i) s += wsum[i];
            int idx = blockIdx.y * gridDim.x + blockIdx.x;
            if (which) g_bp2[idx] = s;
            else       g_bp1[idx] = s;
        }
    }
}

// ---------------- aux kernels ----------------
__global__ void prep_k(const int* __restrict__ hidden) {
    size_t N = (size_t)BATCH * GG;
    for (size_t i = (size_t)blockIdx.x * blockDim.x + threadIdx.x; i < N;
         i += (size_t)gridDim.x * blockDim.x) {
        size_t row = i >> 10;
        int col = (int)(i & 1023);
        g_HA[i] = (float)hidden[row * HS + GG + col] * (1.0f / 8388608.0f);
    }
}

__global__ void final_k(float* __restrict__ out, const int* __restrict__ slice_ptr) {
    __shared__ double sm[256];
    double s = 0.0;
    for (int i = threadIdx.x; i < 512; i += 256) s += g_bp1[i] + g_bp2[i];
    sm[threadIdx.x] = s;
    __syncthreads();
    for (int o = 128; o > 0; o >>= 1) {
        if (threadIdx.x < (unsigned)o) sm[threadIdx.x] += sm[threadIdx.x + o];
        __syncthreads();
    }
    if (threadIdx.x == 0) {
        int slice = slice_ptr ? slice_ptr[0] : 0;
        out[(size_t)2 * BATCH * HS] =
            (float)(sm[0] + 32.0 * (double)slice * (double)BATCH);
    }
}

extern "C" void kernel_launch(void* const* d_in, const int* in_sizes, int n_in,
                              void* d_out, int out_size) {
    (void)in_sizes; (void)out_size;
    const float* x      = (const float*)d_in[0];
    const int*   hidden = (const int*)d_in[1];
    const float* Wzr1   = (const float*)d_in[2];
    const float* bzr1   = (const float*)d_in[3];
    const float* Wg1    = (const float*)d_in[4];
    const float* bg1    = (const float*)d_in[5];
    const float* Wzr2   = (const float*)d_in[6];
    const float* bzr2   = (const float*)d_in[7];
    const float* Wg2    = (const float*)d_in[8];
    const float* bg2    = (const float*)d_in[9];
    const int*   slice  = (n_in > 10) ? (const int*)d_in[10] : nullptr;
    float* out = (float*)d_out;

    cudaFuncSetAttribute(gemm_k<0>, cudaFuncAttributeMaxDynamicSharedMemorySize, SMEM_TOTAL);
    cudaFuncSetAttribute(gemm_k<1>, cudaFuncAttributeMaxDynamicSharedMemorySize, SMEM_TOTAL);

    // HA = h2_fl
    prep_k<<<4096, 256>>>(hidden);

    // zr1: z1 -> g_Z, HB = r1*HA, bits1 partials (slice-aware) -> g_bp1
    gemm_k<0><<<dim3(HS / BN, BATCH / BM), 256, SMEM_TOTAL>>>(
        x, Wzr1, bzr1, HS, 0, nullptr, 0, nullptr, 0, slice, 0);

    // g1: h1 update; rec/out cols [0,1024); HA = h1_fl
    gemm_k<1><<<dim3(GG / BN, BATCH / BM), 256, SMEM_TOTAL>>>(
        x, Wg1, bg1, GG, 1, hidden, 0, out, 1, nullptr, 0);

    // zr2: z2 -> g_Z, HB = r2*h1_fl, bits2 partials (all cols) -> g_bp2
    gemm_k<0><<<dim3(HS / BN, BATCH / BM), 256, SMEM_TOTAL>>>(
        x, Wzr2, bzr2, HS, 0, nullptr, 0, nullptr, 0, nullptr, 1);

    // g2: h2 update; rec/out cols [1024,2048)
    gemm_k<1><<<dim3(GG / BN, BATCH / BM), 256, SMEM_TOTAL>>>(
        x, Wg2, bg2, GG, 1, hidden, 1024, out, 0, nullptr, 0);

    final_k<<<1, 256>>>(out, slice);
}

// round 9
// speedup vs baseline: 1.5404x; 1.5404x over previous
#include <cuda_runtime.h>
#include <cstdint>

typedef long long ll;

#define BATCH 8192
#define INS   1024
#define GG    1024
#define HS    2048
#define KTOT  2048

#define BM 128
#define BN 256
#define BK 32
#define NKI (KTOT/BK)     // 64 K-stages
#define STAGES 4

#define A_BYTES (BM*BK*4)     // 16384
#define B_BYTES (BN*BK*4)     // 32768
#define A_OFF  0
#define B_OFF  (A_OFF + STAGES*A_BYTES)
#define SMEM_TOTAL (B_OFF + STAGES*B_BYTES)   // 196608

#define SW(o) ((o) ^ (((o)>>3)&0x70))

// ---------------- scratch ----------------
__device__ float g_HA[(size_t)BATCH * GG];   // h2_fl, later h1_fl
__device__ float g_HB[(size_t)BATCH * GG];   // r * h_fl
__device__ float g_Z [(size_t)BATCH * GG];   // z1, later z2
__device__ float g_WT[(size_t)KTOT * HS];    // transposed weight [N][K]
__device__ double g_bp1[512];
__device__ double g_bp2[512];

// ---------------- helpers ----------------
__device__ __forceinline__ uint32_t smaddr(const void* p) {
    return (uint32_t)__cvta_generic_to_shared(p);
}
__device__ __forceinline__ void cp16(uint32_t d, const void* s) {
    asm volatile("cp.async.cg.shared.global [%0], [%1], 16;\n" :: "r"(d), "l"(s));
}
__device__ __forceinline__ void cpcommit() { asm volatile("cp.async.commit_group;\n" ::); }
template<int N> __device__ __forceinline__ void cpwait() {
    asm volatile("cp.async.wait_group %0;\n" :: "n"(N));
}

// legacy m16n8k8 tf32 mma (valid on base sm_103 target)
__device__ __forceinline__ void mma_tf32(float* d, const uint32_t* a, const uint32_t* b) {
    asm volatile(
        "mma.sync.aligned.m16n8k8.row.col.f32.tf32.tf32.f32 "
        "{%0,%1,%2,%3}, {%4,%5,%6,%7}, {%8,%9}, {%0,%1,%2,%3};\n"
        : "+f"(d[0]), "+f"(d[1]), "+f"(d[2]), "+f"(d[3])
        : "r"(a[0]), "r"(a[1]), "r"(a[2]), "r"(a[3]), "r"(b[0]), "r"(b[1]));
}

__device__ __forceinline__ float sigf(float v) { return 1.0f / (1.0f + expf(-v)); }
__device__ __forceinline__ void hupd(float pre, float z, int h, float* rec, float* oh) {
    float gv = tanhf(pre);
    ll zf = (ll)(z * 1024.0f); if (zf < 1) zf = 1;
    int hi = (int)((((ll)h * zf) >> 10) + (ll)((1.0f - z) * gv * 8388608.0f));
    *rec = (float)hi; *oh = (float)hi * (1.0f / 8388608.0f);
}

// ---------------- GEMM with fused epilogue ----------------
// B is read from g_WT ([N][K], 128B rows) — this keeps the inner-loop B
// addressing ni-invariant (cheap registers; the round-5 direct-W [k][n]
// layout blew regs to 234 and tripled runtime).
// EPI 0: zr GEMM. cols<1024: z -> g_Z + fused bits partial -> g_bp{1,2}[cta].
//        cols>=1024: g_HB = sig * g_HA.
// EPI 1: g GEMM. tanh + fixed-point hidden update; writes rec + out (+ g_HA).
template<int EPI>
__global__ void __launch_bounds__(256, 1) gemm_k(
    const float* __restrict__ x,
    const float* __restrict__ bias,
    int hinSel,
    const int* __restrict__ hidden,
    int hoff,
    float* __restrict__ out,
    int writeHA,
    const int* __restrict__ slice_ptr,
    int which)
{
    extern __shared__ char smem[];
    const uint32_t sbase = smaddr(smem);
    const int tid  = threadIdx.x;
    const int wid  = tid >> 5, lane = tid & 31;
    const int bm0  = blockIdx.y * BM;
    const int bn0  = blockIdx.x * BN;
    const float* Hin = hinSel ? g_HB : g_HA;

    auto load_stage = [&](int kt, int buf) {
        const int kbase = kt * BK;
        const float* asrc = (kbase < INS) ? (x + kbase) : (Hin + (kbase - INS));
        const uint32_t abase = sbase + A_OFF + buf * A_BYTES;
        #pragma unroll
        for (int i = 0; i < 4; ++i) {
            int q = tid + i * 256;
            int row = q >> 3, kc = q & 7;
            uint32_t off = row * 128 + kc * 16;
            cp16(abase + SW(off), asrc + (size_t)(bm0 + row) * INS + kc * 4);
        }
        const uint32_t bbase = sbase + B_OFF + buf * B_BYTES;
        #pragma unroll
        for (int i = 0; i < 8; ++i) {
            int q = tid + i * 256;
            int row = q >> 3, kc = q & 7;
            uint32_t off = row * 128 + kc * 16;
            cp16(bbase + SW(off), g_WT + (size_t)(bn0 + row) * KTOT + kbase + kc * 4);
        }
    };

    #pragma unroll
    for (int s = 0; s < STAGES - 1; ++s) { load_stage(s, s); cpcommit(); }

    // 8 warps: 2(M) x 4(N); warp tile 64x64
    const int wm0 = (wid >> 2) * 64;
    const int wn0 = (wid & 3) * 64;
    const int rm = lane >> 2, ck = lane & 3;
    float acc[4][8][4];
    #pragma unroll
    for (int i = 0; i < 4; ++i)
        #pragma unroll
        for (int j = 0; j < 8; ++j)
            #pragma unroll
            for (int e = 0; e < 4; ++e) acc[i][j][e] = 0.0f;

    for (int kt = 0; kt < NKI; ++kt) {
        const int buf = kt & (STAGES - 1);
        const int lt = kt + STAGES - 1;
        if (lt < NKI) load_stage(lt, lt & (STAGES - 1));
        cpcommit();
        cpwait<STAGES - 1>();
        __syncthreads();

        const char* At = smem + A_OFF + buf * A_BYTES;
        const char* Bt = smem + B_OFF + buf * B_BYTES;
        #pragma unroll
        for (int ks = 0; ks < 4; ++ks) {
            const int k0 = ks * 8;
            uint32_t af[4][4];
            #pragma unroll
            for (int mi = 0; mi < 4; ++mi) {
                int m1 = wm0 + mi * 16 + rm;
                int m2 = m1 + 8;
                uint32_t o;
                o = m1 * 128 + (((k0 + ck) * 4)     ^ ((m1 & 7) << 4));
                af[mi][0] = *(const uint32_t*)(At + o);
                o = m2 * 128 + (((k0 + ck) * 4)     ^ ((m2 & 7) << 4));
                af[mi][1] = *(const uint32_t*)(At + o);
                o = m1 * 128 + (((k0 + ck + 4) * 4) ^ ((m1 & 7) << 4));
                af[mi][2] = *(const uint32_t*)(At + o);
                o = m2 * 128 + (((k0 + ck + 4) * 4) ^ ((m2 & 7) << 4));
                af[mi][3] = *(const uint32_t*)(At + o);
            }
            #pragma unroll
            for (int ni = 0; ni < 8; ++ni) {
                int n = wn0 + ni * 8 + rm;
                uint32_t bf[2], o;
                o = n * 128 + (((k0 + ck) * 4)     ^ ((n & 7) << 4));
                bf[0] = *(const uint32_t*)(Bt + o);
                o = n * 128 + (((k0 + ck + 4) * 4) ^ ((n & 7) << 4));
                bf[1] = *(const uint32_t*)(Bt + o);
                #pragma unroll
                for (int mi = 0; mi < 4; ++mi)
                    mma_tf32(acc[mi][ni], af[mi], bf);
            }
        }
        __syncthreads();
    }

    // ---------------- epilogue ----------------
    const int c2 = (lane & 3) * 2;
    float bl = 0.0f;                               // fused bits partial (EPI0)
    const int slice = (EPI == 0 && slice_ptr) ? __ldg(slice_ptr) : 0;

    #pragma unroll
    for (int mi = 0; mi < 4; ++mi) {
        #pragma unroll
        for (int rr = 0; rr < 2; ++rr) {
            int m = bm0 + wm0 + mi * 16 + rm + rr * 8;
            #pragma unroll
            for (int ni = 0; ni < 8; ++ni) {
                int n = bn0 + wn0 + ni * 8 + c2;
                float p0 = acc[mi][ni][rr * 2 + 0] + bias[n];
                float p1 = acc[mi][ni][rr * 2 + 1] + bias[n + 1];
                if (EPI == 0) {
                    float s0 = sigf(p0), s1 = sigf(p1);
                    if (n < GG) {
                        float2 z; z.x = 0.875f * s0 + 0.125f; z.y = 0.875f * s1 + 0.125f;
                        *(float2*)&g_Z[(size_t)m * GG + n] = z;
                        if (n     >= slice) bl -= log2f(z.x);
                        if (n + 1 >= slice) bl -= log2f(z.y);
                    } else {
                        size_t j = (size_t)m * GG + (n - GG);
                        float2 ha = *(const float2*)&g_HA[j];
                        float2 hb; hb.x = s0 * ha.x; hb.y = s1 * ha.y;
                        *(float2*)&g_HB[j] = hb;
                    }
                } else {
                    size_t zj = (size_t)m * GG + n;
                    float2 zv = *(const float2*)&g_Z[zj];
                    int2 hv = *(const int2*)&hidden[(size_t)m * HS + hoff + n];
                    float2 recf, ohf;
                    hupd(p0, zv.x, hv.x, &recf.x, &ohf.x);
                    hupd(p1, zv.y, hv.y, &recf.y, &ohf.y);
                    *(float2*)&out[(size_t)m * HS + hoff + n] = recf;
                    *(float2*)&out[(size_t)BATCH * HS + (size_t)m * HS + hoff + n] = ohf;
                    if (writeHA) *(float2*)&g_HA[zj] = ohf;
                }
            }
        }
    }

    if (EPI == 0) {
        #pragma unroll
        for (int o = 16; o > 0; o >>= 1)
            bl += __shfl_down_sync(0xFFFFFFFFu, bl, o);
        __shared__ double wsum[8];
        if (lane == 0) wsum[wid] = (double)bl;
        __syncthreads();
        if (tid == 0) {
            double s = 0.0;
            #pragma unroll
            for (int i = 0; i < 8; ++i) s += wsum[i];
            int idx = blockIdx.y * gridDim.x + blockIdx.x;
            if (which) g_bp2[idx] = s;
            else       g_bp1[idx] = s;
        }
    }
}

// ---------------- aux kernels ----------------
// WT[n][k] = W[k][n]
__global__ void transpose_k(const float* __restrict__ W, int N) {
    __shared__ float t[32][33];
    int n0 = blockIdx.x * 32, k0 = blockIdx.y * 32;
    int tx = threadIdx.x, ty = threadIdx.y;   // 32 x 8
    #pragma unroll
    for (int i = 0; i < 32; i += 8)
        t[ty + i][tx] = W[(size_t)(k0 + ty + i) * N + n0 + tx];
    __syncthreads();
    #pragma unroll
    for (int i = 0; i < 32; i += 8)
        g_WT[(size_t)(n0 + ty + i) * KTOT + k0 + tx] = t[tx][ty + i];
}

__global__ void prep_k(const int* __restrict__ hidden) {
    size_t N = (size_t)BATCH * GG;
    for (size_t i = (size_t)blockIdx.x * blockDim.x + threadIdx.x; i < N;
         i += (size_t)gridDim.x * blockDim.x) {
        size_t row = i >> 10;
        int col = (int)(i & 1023);
        g_HA[i] = (float)hidden[row * HS + GG + col] * (1.0f / 8388608.0f);
    }
}

__global__ void final_k(float* __restrict__ out, const int* __restrict__ slice_ptr) {
    __shared__ double sm[256];
    double s = 0.0;
    for (int i = threadIdx.x; i < 512; i += 256) s += g_bp1[i] + g_bp2[i];
    sm[threadIdx.x] = s;
    __syncthreads();
    for (int o = 128; o > 0; o >>= 1) {
        if (threadIdx.x < (unsigned)o) sm[threadIdx.x] += sm[threadIdx.x + o];
        __syncthreads();
    }
    if (threadIdx.x == 0) {
        int slice = slice_ptr ? slice_ptr[0] : 0;
        out[(size_t)2 * BATCH * HS] =
            (float)(sm[0] + 32.0 * (double)slice * (double)BATCH);
    }
}

extern "C" void kernel_launch(void* const* d_in, const int* in_sizes, int n_in,
                              void* d_out, int out_size) {
    (void)in_sizes; (void)out_size;
    const float* x      = (const float*)d_in[0];
    const int*   hidden = (const int*)d_in[1];
    const float* Wzr1   = (const float*)d_in[2];
    const float* bzr1   = (const float*)d_in[3];
    const float* Wg1    = (const float*)d_in[4];
    const float* bg1    = (const float*)d_in[5];
    const float* Wzr2   = (const float*)d_in[6];
    const float* bzr2   = (const float*)d_in[7];
    const float* Wg2    = (const float*)d_in[8];
    const float* bg2    = (const float*)d_in[9];
    const int*   slice  = (n_in > 10) ? (const int*)d_in[10] : nullptr;
    float* out = (float*)d_out;

    cudaFuncSetAttribute(gemm_k<0>, cudaFuncAttributeMaxDynamicSharedMemorySize, SMEM_TOTAL);
    cudaFuncSetAttribute(gemm_k<1>, cudaFuncAttributeMaxDynamicSharedMemorySize, SMEM_TOTAL);

    // HA = h2_fl
    prep_k<<<4096, 256>>>(hidden);

    // zr1: z1 -> g_Z, HB = r1*HA, bits1 partials (slice-aware) -> g_bp1
    transpose_k<<<dim3(64, 64), dim3(32, 8)>>>(Wzr1, HS);
    gemm_k<0><<<dim3(HS / BN, BATCH / BM), 256, SMEM_TOTAL>>>(
        x, bzr1, 0, nullptr, 0, nullptr, 0, slice, 0);

    // g1: h1 update; rec/out cols [0,1024); HA = h1_fl
    transpose_k<<<dim3(32, 64), dim3(32, 8)>>>(Wg1, GG);
    gemm_k<1><<<dim3(GG / BN, BATCH / BM), 256, SMEM_TOTAL>>>(
        x, bg1, 1, hidden, 0, out, 1, nullptr, 0);

    // zr2: z2 -> g_Z, HB = r2*h1_fl, bits2 partials (all cols) -> g_bp2
    transpose_k<<<dim3(64, 64), dim3(32, 8)>>>(Wzr2, HS);
    gemm_k<0><<<dim3(HS / BN, BATCH / BM), 256, SMEM_TOTAL>>>(
        x, bzr2, 0, nullptr, 0, nullptr, 0, nullptr, 1);

    // g2: h2 update; rec/out cols [1024,2048)
    transpose_k<<<dim3(32, 64), dim3(32, 8)>>>(Wg2, GG);
    gemm_k<1><<<dim3(GG / BN, BATCH / BM), 256, SMEM_TOTAL>>>(
        x, bg2, 1, hidden, 1024, out, 0, nullptr, 0);

    final_k<<<1, 256>>>(out, slice);
}

// round 11
// speedup vs baseline: 1.7350x; 1.1263x over previous
#include <cuda_runtime.h>
#include <cstdint>

typedef long long ll;

#define BATCH 8192
#define INS   1024
#define GG    1024
#define HS    2048
#define KTOT  2048

#define BM 128
#define BN 256
#define BK 32
#define NKI (KTOT/BK)     // 64 K-stages
#define STAGES 4

#define A_BYTES (BM*BK*4)     // 16384
#define B_BYTES (BN*BK*4)     // 32768
#define A_OFF  1024
#define B_OFF  (A_OFF + STAGES*A_BYTES)
#define SMEM_TOTAL (B_OFF + STAGES*B_BYTES)   // 197632

#define SW(o) ((o) ^ (((o)>>3)&0x70))

// ---------------- scratch ----------------
__device__ float g_HA[(size_t)BATCH * GG];   // h2_fl, later h1_fl
__device__ float g_HB[(size_t)BATCH * GG];   // r * h_fl
__device__ float g_Z [(size_t)BATCH * GG];   // z1, later z2
__device__ float g_WT[(size_t)KTOT * HS];    // transposed weight [N][K]
__device__ double g_bp1[512];
__device__ double g_bp2[512];

// ---------------- helpers ----------------
__device__ __forceinline__ uint32_t smaddr(const void* p) {
    return (uint32_t)__cvta_generic_to_shared(p);
}
__device__ __forceinline__ void cp16(uint32_t d, const void* s) {
    asm volatile("cp.async.cg.shared.global [%0], [%1], 16;\n" :: "r"(d), "l"(s));
}
__device__ __forceinline__ void cpcommit() { asm volatile("cp.async.commit_group;\n" ::); }
template<int N> __device__ __forceinline__ void cpwait() {
    asm volatile("cp.async.wait_group %0;\n" :: "n"(N));
}

// legacy m16n8k8 tf32 mma (valid on base sm_103 target)
__device__ __forceinline__ void mma_tf32(float* d, const uint32_t* a, const uint32_t* b) {
    asm volatile(
        "mma.sync.aligned.m16n8k8.row.col.f32.tf32.tf32.f32 "
        "{%0,%1,%2,%3}, {%4,%5,%6,%7}, {%8,%9}, {%0,%1,%2,%3};\n"
        : "+f"(d[0]), "+f"(d[1]), "+f"(d[2]), "+f"(d[3])
        : "r"(a[0]), "r"(a[1]), "r"(a[2]), "r"(a[3]), "r"(b[0]), "r"(b[1]));
}

__device__ __forceinline__ float sigf(float v) { return 1.0f / (1.0f + expf(-v)); }
__device__ __forceinline__ void hupd(float pre, float z, int h, float* rec, float* oh) {
    float gv = tanhf(pre);
    ll zf = (ll)(z * 1024.0f); if (zf < 1) zf = 1;
    int hi = (int)((((ll)h * zf) >> 10) + (ll)((1.0f - z) * gv * 8388608.0f));
    *rec = (float)hi; *oh = (float)hi * (1.0f / 8388608.0f);
}

// ---------------- GEMM (FROZEN: byte-exact round-3 fallback path) ----------------
// EPI 0: zr GEMM. cols<1024: z=0.875*sig+0.125 -> g_Z; cols>=1024: g_HB = sig*g_HA
// EPI 1: g GEMM. tanh + fixed-point hidden update, writes rec/out (+ g_HA).
template<int EPI>
__global__ void __launch_bounds__(256, 1) gemm_tc(
    const float* __restrict__ x,
    const float* __restrict__ bias,
    int hinSel,
    const int* __restrict__ hidden,
    int hoff,
    float* __restrict__ out,
    int writeHA)
{
    extern __shared__ char smem[];
    const uint32_t sbase = smaddr(smem);
    const int tid  = threadIdx.x;
    const int wid  = tid >> 5, lane = tid & 31;
    const int bm0  = blockIdx.y * BM;
    const int bn0  = blockIdx.x * BN;
    const float* Hin = hinSel ? g_HB : g_HA;

    auto load_stage = [&](int kt, int buf) {
        const int kbase = kt * BK;
        const float* asrc = (kbase < INS) ? (x + kbase) : (Hin + (kbase - INS));
        const uint32_t abase = sbase + A_OFF + buf * A_BYTES;
        #pragma unroll
        for (int i = 0; i < 4; ++i) {
            int q = tid + i * 256;
            int row = q >> 3, kc = q & 7;
            uint32_t off = row * 128 + kc * 16;
            cp16(abase + SW(off), asrc + (size_t)(bm0 + row) * INS + kc * 4);
        }
        const uint32_t bbase = sbase + B_OFF + buf * B_BYTES;
        #pragma unroll
        for (int i = 0; i < 8; ++i) {
            int q = tid + i * 256;
            int row = q >> 3, kc = q & 7;
            uint32_t off = row * 128 + kc * 16;
            cp16(bbase + SW(off), g_WT + (size_t)(bn0 + row) * KTOT + kbase + kc * 4);
        }
    };

    #pragma unroll
    for (int s = 0; s < STAGES - 1; ++s) { load_stage(s, s); cpcommit(); }

    // 8 warps: 2(M) x 4(N); warp tile 64x64
    const int wm0 = (wid >> 2) * 64;
    const int wn0 = (wid & 3) * 64;
    const int rm = lane >> 2, ck = lane & 3;
    float acc[4][8][4];
    #pragma unroll
    for (int i = 0; i < 4; ++i)
        #pragma unroll
        for (int j = 0; j < 8; ++j)
            #pragma unroll
            for (int e = 0; e < 4; ++e) acc[i][j][e] = 0.0f;

    for (int kt = 0; kt < NKI; ++kt) {
        const int buf = kt & (STAGES - 1);
        const int lt = kt + STAGES - 1;
        if (lt < NKI) load_stage(lt, lt & (STAGES - 1));
        cpcommit();
        cpwait<STAGES - 1>();
        __syncthreads();

        const char* At = smem + A_OFF + buf * A_BYTES;
        const char* Bt = smem + B_OFF + buf * B_BYTES;
        #pragma unroll
        for (int ks = 0; ks < 4; ++ks) {
            const int k0 = ks * 8;
            uint32_t af[4][4];
            #pragma unroll
            for (int mi = 0; mi < 4; ++mi) {
                int m1 = wm0 + mi * 16 + rm;
                int m2 = m1 + 8;
                uint32_t o;
                o = m1 * 128 + (((k0 + ck) * 4)     ^ ((m1 & 7) << 4));
                af[mi][0] = *(const uint32_t*)(At + o);
                o = m2 * 128 + (((k0 + ck) * 4)     ^ ((m2 & 7) << 4));
                af[mi][1] = *(const uint32_t*)(At + o);
                o = m1 * 128 + (((k0 + ck + 4) * 4) ^ ((m1 & 7) << 4));
                af[mi][2] = *(const uint32_t*)(At + o);
                o = m2 * 128 + (((k0 + ck + 4) * 4) ^ ((m2 & 7) << 4));
                af[mi][3] = *(const uint32_t*)(At + o);
            }
            #pragma unroll
            for (int ni = 0; ni < 8; ++ni) {
                int n = wn0 + ni * 8 + rm;
                uint32_t bf[2], o;
                o = n * 128 + (((k0 + ck) * 4)     ^ ((n & 7) << 4));
                bf[0] = *(const uint32_t*)(Bt + o);
                o = n * 128 + (((k0 + ck + 4) * 4) ^ ((n & 7) << 4));
                bf[1] = *(const uint32_t*)(Bt + o);
                #pragma unroll
                for (int mi = 0; mi < 4; ++mi)
                    mma_tf32(acc[mi][ni], af[mi], bf);
            }
        }
        __syncthreads();
    }

    // ---- epilogue (round-3 form) ----
    const int c2 = (lane & 3) * 2;
    #pragma unroll
    for (int mi = 0; mi < 4; ++mi) {
        #pragma unroll
        for (int rr = 0; rr < 2; ++rr) {
            int m = bm0 + wm0 + mi * 16 + rm + rr * 8;
            #pragma unroll
            for (int ni = 0; ni < 8; ++ni) {
                int n = bn0 + wn0 + ni * 8 + c2;
                float p0 = acc[mi][ni][rr * 2 + 0] + bias[n];
                float p1 = acc[mi][ni][rr * 2 + 1] + bias[n + 1];
                if (EPI == 0) {
                    float s0 = sigf(p0), s1 = sigf(p1);
                    if (n < GG) {
                        float2 z; z.x = 0.875f * s0 + 0.125f; z.y = 0.875f * s1 + 0.125f;
                        *(float2*)&g_Z[(size_t)m * GG + n] = z;
                    } else {
                        size_t j = (size_t)m * GG + (n - GG);
                        float2 ha = *(const float2*)&g_HA[j];
                        float2 hb; hb.x = s0 * ha.x; hb.y = s1 * ha.y;
                        *(float2*)&g_HB[j] = hb;
                    }
                } else {
                    size_t zj = (size_t)m * GG + n;
                    float2 zv = *(const float2*)&g_Z[zj];
                    int2 hv = *(const int2*)&hidden[(size_t)m * HS + hoff + n];
                    float2 recf, ohf;
                    hupd(p0, zv.x, hv.x, &recf.x, &ohf.x);
                    hupd(p1, zv.y, hv.y, &recf.y, &ohf.y);
                    *(float2*)&out[(size_t)m * HS + hoff + n] = recf;
                    *(float2*)&out[(size_t)BATCH * HS + (size_t)m * HS + hoff + n] = ohf;
                    if (writeHA) *(float2*)&g_HA[zj] = ohf;
                }
            }
        }
    }
}

// ---------------- aux kernels ----------------
// WT[n][k] = W[k][n]
__global__ void transpose_k(const float* __restrict__ W, int N) {
    __shared__ float t[32][33];
    int n0 = blockIdx.x * 32, k0 = blockIdx.y * 32;
    int tx = threadIdx.x, ty = threadIdx.y;   // 32 x 8
    #pragma unroll
    for (int i = 0; i < 32; i += 8)
        t[ty + i][tx] = W[(size_t)(k0 + ty + i) * N + n0 + tx];
    __syncthreads();
    #pragma unroll
    for (int i = 0; i < 32; i += 8)
        g_WT[(size_t)(n0 + ty + i) * KTOT + k0 + tx] = t[tx][ty + i];
}

// HA = h2_fl = hidden[:, G:] / 2^23  (vectorized int4 -> float4)
__global__ void prep_k(const int* __restrict__ hidden) {
    size_t N4 = (size_t)BATCH * GG / 4;
    for (size_t i = (size_t)blockIdx.x * blockDim.x + threadIdx.x; i < N4;
         i += (size_t)gridDim.x * blockDim.x) {
        size_t row = i >> 8;                   // 256 float4 per row
        int c4 = (int)(i & 255) * 4;
        int4 h = *(const int4*)&hidden[row * HS + GG + c4];
        float4 f;
        f.x = (float)h.x * (1.0f / 8388608.0f);
        f.y = (float)h.y * (1.0f / 8388608.0f);
        f.z = (float)h.z * (1.0f / 8388608.0f);
        f.w = (float)h.w * (1.0f / 8388608.0f);
        *(float4*)&g_HA[i * 4] = f;
    }
}

// -log2(z) reduction; float inner accumulator (fp64 only at block combine).
// which selects g_bp1 / g_bp2 INSIDE device code (device symbols can't be
// passed from host).
__global__ void bits_k(const int* __restrict__ slice_ptr, int which) {
    const int slice = slice_ptr ? __ldg(slice_ptr) : 0;
    float s = 0.0f;
    size_t N4 = (size_t)BATCH * GG / 4;
    for (size_t i = (size_t)blockIdx.x * blockDim.x + threadIdx.x; i < N4;
         i += (size_t)gridDim.x * blockDim.x) {
        int col = (int)(i & 255) * 4;
        float4 z = *(const float4*)&g_Z[i * 4];
        if (col     >= slice) s -= log2f(z.x);
        if (col + 1 >= slice) s -= log2f(z.y);
        if (col + 2 >= slice) s -= log2f(z.z);
        if (col + 3 >= slice) s -= log2f(z.w);
    }
    // deterministic reduce: warp shfl (float), then block combine in double
    #pragma unroll
    for (int o = 16; o > 0; o >>= 1)
        s += __shfl_down_sync(0xFFFFFFFFu, s, o);
    __shared__ double sm[8];
    int wid = threadIdx.x >> 5, lane = threadIdx.x & 31;
    if (lane == 0) sm[wid] = (double)s;
    __syncthreads();
    if (threadIdx.x == 0) {
        double t = 0.0;
        #pragma unroll
        for (int i = 0; i < 8; ++i) t += sm[i];
        if (which) g_bp2[blockIdx.x] = t;
        else       g_bp1[blockIdx.x] = t;
    }
}

__global__ void final_k(float* __restrict__ out, const int* __restrict__ slice_ptr) {
    __shared__ double sm[256];
    double s = 0.0;
    for (int i = threadIdx.x; i < 512; i += 256) s += g_bp1[i] + g_bp2[i];
    sm[threadIdx.x] = s;
    __syncthreads();
    for (int o = 128; o > 0; o >>= 1) {
        if (threadIdx.x < (unsigned)o) sm[threadIdx.x] += sm[threadIdx.x + o];
        __syncthreads();
    }
    if (threadIdx.x == 0) {
        int slice = slice_ptr ? slice_ptr[0] : 0;
        out[(size_t)2 * BATCH * HS] =
            (float)(sm[0] + 32.0 * (double)slice * (double)BATCH);
    }
}

extern "C" void kernel_launch(void* const* d_in, const int* in_sizes, int n_in,
                              void* d_out, int out_size) {
    (void)in_sizes; (void)out_size;
    const float* x      = (const float*)d_in[0];
    const int*   hidden = (const int*)d_in[1];
    const float* Wzr1   = (const float*)d_in[2];
    const float* bzr1   = (const float*)d_in[3];
    const float* Wg1    = (const float*)d_in[4];
    const float* bg1    = (const float*)d_in[5];
    const float* Wzr2   = (const float*)d_in[6];
    const float* bzr2   = (const float*)d_in[7];
    const float* Wg2    = (const float*)d_in[8];
    const float* bg2    = (const float*)d_in[9];
    const int*   slice  = (n_in > 10) ? (const int*)d_in[10] : nullptr;
    float* out = (float*)d_out;

    cudaFuncSetAttribute(gemm_tc<0>, cudaFuncAttributeMaxDynamicSharedMemorySize, SMEM_TOTAL);
    cudaFuncSetAttribute(gemm_tc<1>, cudaFuncAttributeMaxDynamicSharedMemorySize, SMEM_TOTAL);

    prep_k<<<2048, 256>>>(hidden);

    // zr1: z1 -> g_Z, HB = r1*HA
    transpose_k<<<dim3(64, 64), dim3(32, 8)>>>(Wzr1, HS);
    gemm_tc<0><<<dim3(HS / BN, BATCH / BM), 256, SMEM_TOTAL>>>(x, bzr1, 0, nullptr, 0, nullptr, 0);
    bits_k<<<512, 256>>>(slice, 0);

    // g1: h1 update; rec/out cols [0,1024); HA = h1_fl
    transpose_k<<<dim3(32, 64), dim3(32, 8)>>>(Wg1, GG);
    gemm_tc<1><<<dim3(GG / BN, BATCH / BM), 256, SMEM_TOTAL>>>(x, bg1, 1, hidden, 0, out, 1);

    // zr2: z2 -> g_Z, HB = r2*h1_fl
    transpose_k<<<dim3(64, 64), dim3(32, 8)>>>(Wzr2, HS);
    gemm_tc<0><<<dim3(HS / BN, BATCH / BM), 256, SMEM_TOTAL>>>(x, bzr2, 0, nullptr, 0, nullptr, 0);
    bits_k<<<512, 256>>>(nullptr, 1);

    // g2: h2 update; rec/out cols [1024,2048)
    transpose_k<<<dim3(32, 64), dim3(32, 8)>>>(Wg2, GG);
    gemm_tc<1><<<dim3(GG / BN, BATCH / BM), 256, SMEM_TOTAL>>>(x, bg2, 1, hidden, 1024, out, 0);

    final_k<<<1, 256>>>(out, slice);
}